// round 2
// baseline (speedup 1.0000x reference)
#include <cuda_runtime.h>
#include <math.h>

#define NN   32768
#define KK   1024
#define DHH  512
#define EPSF 1e-5f
#define NITER 150
#define FBIG 3.402823466e38f
#define NKELT ((size_t)NN * KK)

typedef unsigned long long ull;

// ---- static device scratch (no allocations allowed) ----
__device__ __align__(16) float g_d[NN * KK];     // 128 MB distances
__device__ float g_a[NN];                        // zz + 2*eps*sz + Dh*eps^2
__device__ float g_b[KK];                        // mm - 2*eps*sm
__device__ float g_relz[NN * 5];                 // row top-5 ascending
__device__ float g_rhoz[NN], g_sigz[NN];
__device__ float g_cspart[64 * KK];              // colsum(S) partials
__device__ float g_icolsum[KK];                  // 1/colsum(S)

// ---- f32x2 helpers ----
__device__ __forceinline__ ull ffma2(ull a, ull b, ull c) {
    ull d;
    asm("fma.rn.f32x2 %0, %1, %2, %3;" : "=l"(d) : "l"(a), "l"(b), "l"(c));
    return d;
}
__device__ __forceinline__ ull dup2(float x) {
    ull r;
    asm("mov.b64 %0, {%1, %1};" : "=l"(r) : "f"(x));
    return r;
}
__device__ __forceinline__ float2 unpk(ull v) {
    float2 r;
    asm("mov.b64 {%0, %1}, %2;" : "=f"(r.x), "=f"(r.y) : "l"(v));
    return r;
}

// ---- sorted smallest-5 insertion ----
#define INS5(v, a0, a1, a2, a3, a4) do {                          \
    float _v = (v);                                               \
    if (_v < a4) {                                                \
        a4 = _v;                                                  \
        if (a4 < a3) { float _t = a3; a3 = a4; a4 = _t; }         \
        if (a3 < a2) { float _t = a2; a2 = a3; a3 = _t; }         \
        if (a2 < a1) { float _t = a1; a1 = a2; a2 = _t; }         \
        if (a1 < a0) { float _t = a0; a0 = a1; a1 = _t; }         \
    }                                                             \
} while (0)

// ======================= K0: row stats =======================
__global__ void k_stats(const float* __restrict__ P, float* __restrict__ out,
                        float c2, float cadd) {
    int row  = blockIdx.x * 8 + (threadIdx.x >> 5);
    int lane = threadIdx.x & 31;
    const float* p = P + (size_t)row * DHH;
    float s = 0.f, ss = 0.f;
#pragma unroll
    for (int q = 0; q < 4; ++q) {
        float4 v = *(const float4*)&p[q * 128 + lane * 4];
        s  += (v.x + v.y) + (v.z + v.w);
        ss += v.x * v.x + v.y * v.y + v.z * v.z + v.w * v.w;
    }
#pragma unroll
    for (int off = 16; off > 0; off >>= 1) {
        s  += __shfl_xor_sync(0xffffffffu, s, off);
        ss += __shfl_xor_sync(0xffffffffu, ss, off);
    }
    if (lane == 0) out[row] = ss + c2 * s + cadd;
}

// ======================= K1: GEMM + distance =======================
// 128x128 tile, BK=8, 256 threads, 8x8/thread via f32x2 (i-paired accumulators)
__global__ void k_gemm(const float* __restrict__ Z, const float* __restrict__ MU) {
    __shared__ __align__(16) float As[2][8][128];
    __shared__ __align__(16) float Bs[2][8][128];

    const int tid = threadIdx.x;
    const int tx = tid & 15;
    const int ty = tid >> 4;
    const int i0 = blockIdx.y * 128;
    const int j0 = blockIdx.x * 128;
    const int lr = tid >> 1;
    const int lc = (tid & 1) * 4;

    const float* zptr = Z  + (size_t)(i0 + lr) * DHH + lc;
    const float* mptr = MU + (size_t)(j0 + lr) * DHH + lc;

    {
        float4 av = *(const float4*)zptr;
        float4 bv = *(const float4*)mptr;
        As[0][lc + 0][lr] = av.x; As[0][lc + 1][lr] = av.y;
        As[0][lc + 2][lr] = av.z; As[0][lc + 3][lr] = av.w;
        Bs[0][lc + 0][lr] = bv.x; Bs[0][lc + 1][lr] = bv.y;
        Bs[0][lc + 2][lr] = bv.z; Bs[0][lc + 3][lr] = bv.w;
    }
    __syncthreads();

    ull acc[4][8];
#pragma unroll
    for (int pi = 0; pi < 4; ++pi)
#pragma unroll
        for (int j = 0; j < 8; ++j) acc[pi][j] = 0ull;

    int cur = 0;
#pragma unroll 1
    for (int kt = 0; kt < DHH / 8; ++kt) {
        float4 nav, nbv;
        const bool more = (kt + 1 < DHH / 8);
        if (more) {
            nav = *(const float4*)(zptr + (kt + 1) * 8);
            nbv = *(const float4*)(mptr + (kt + 1) * 8);
        }
#pragma unroll
        for (int k = 0; k < 8; ++k) {
            ulonglong2 a01 = *(const ulonglong2*)&As[cur][k][ty * 8];
            ulonglong2 a23 = *(const ulonglong2*)&As[cur][k][ty * 8 + 4];
            float4 b0 = *(const float4*)&Bs[cur][k][tx * 8];
            float4 b1 = *(const float4*)&Bs[cur][k][tx * 8 + 4];
            ull bd[8] = { dup2(b0.x), dup2(b0.y), dup2(b0.z), dup2(b0.w),
                          dup2(b1.x), dup2(b1.y), dup2(b1.z), dup2(b1.w) };
#pragma unroll
            for (int j = 0; j < 8; ++j) {
                acc[0][j] = ffma2(a01.x, bd[j], acc[0][j]);
                acc[1][j] = ffma2(a01.y, bd[j], acc[1][j]);
                acc[2][j] = ffma2(a23.x, bd[j], acc[2][j]);
                acc[3][j] = ffma2(a23.y, bd[j], acc[3][j]);
            }
        }
        int nxt = cur ^ 1;
        if (more) {
            As[nxt][lc + 0][lr] = nav.x; As[nxt][lc + 1][lr] = nav.y;
            As[nxt][lc + 2][lr] = nav.z; As[nxt][lc + 3][lr] = nav.w;
            Bs[nxt][lc + 0][lr] = nbv.x; Bs[nxt][lc + 1][lr] = nbv.y;
            Bs[nxt][lc + 2][lr] = nbv.z; Bs[nxt][lc + 3][lr] = nbv.w;
        }
        __syncthreads();
        cur = nxt;
    }

    float ag[8], bg[8];
#pragma unroll
    for (int ii = 0; ii < 8; ++ii) ag[ii] = g_a[i0 + ty * 8 + ii];
#pragma unroll
    for (int j = 0; j < 8; ++j) bg[j] = g_b[j0 + tx * 8 + j];

#pragma unroll
    for (int pi = 0; pi < 4; ++pi) {
        float o0[8], o1[8];
#pragma unroll
        for (int j = 0; j < 8; ++j) {
            float2 v = unpk(acc[pi][j]);
            o0[j] = sqrtf(fmaxf(ag[2 * pi]     + bg[j] - 2.0f * v.x, 0.0f));
            o1[j] = sqrtf(fmaxf(ag[2 * pi + 1] + bg[j] - 2.0f * v.y, 0.0f));
        }
        size_t r0 = (size_t)(i0 + ty * 8 + 2 * pi) * KK + (j0 + tx * 8);
        *(float4*)&g_d[r0]      = make_float4(o0[0], o0[1], o0[2], o0[3]);
        *(float4*)&g_d[r0 + 4]  = make_float4(o0[4], o0[5], o0[6], o0[7]);
        *(float4*)&g_d[r0 + KK]     = make_float4(o1[0], o1[1], o1[2], o1[3]);
        *(float4*)&g_d[r0 + KK + 4] = make_float4(o1[4], o1[5], o1[6], o1[7]);
    }
}

// ======================= K2: row top-5 =======================
__global__ void k_rowtop5() {
    int row  = blockIdx.x * 8 + (threadIdx.x >> 5);
    int lane = threadIdx.x & 31;
    const float* dr = g_d + (size_t)row * KK;
    float t0 = FBIG, t1 = FBIG, t2 = FBIG, t3 = FBIG, t4 = FBIG;
#pragma unroll
    for (int q = 0; q < 32; ++q) {
        float v = dr[lane + (q << 5)];
        INS5(v, t0, t1, t2, t3, t4);
    }
#pragma unroll
    for (int off = 16; off > 0; off >>= 1) {
        float s0 = __shfl_xor_sync(0xffffffffu, t0, off);
        float s1 = __shfl_xor_sync(0xffffffffu, t1, off);
        float s2 = __shfl_xor_sync(0xffffffffu, t2, off);
        float s3 = __shfl_xor_sync(0xffffffffu, t3, off);
        float s4 = __shfl_xor_sync(0xffffffffu, t4, off);
        INS5(s0, t0, t1, t2, t3, t4);
        INS5(s1, t0, t1, t2, t3, t4);
        INS5(s2, t0, t1, t2, t3, t4);
        INS5(s3, t0, t1, t2, t3, t4);
        INS5(s4, t0, t1, t2, t3, t4);
    }
    if (lane == 0) {
        float* o = g_relz + (size_t)row * 5;
        o[0] = t0; o[1] = t1; o[2] = t2; o[3] = t3; o[4] = t4;
    }
}

// ======================= K3: sigma bisection (z rows only) =======================
__global__ void k_solve() {
    int r = blockIdx.x * 256 + threadIdx.x;
    const float* rl = g_relz + (size_t)r * 5;
    float rho = rl[0];
    float e1 = rl[1] - rho, e2 = rl[2] - rho, e3 = rl[3] - rho, e4 = rl[4] - rho;
    float m0 = 0.f, m1 = 10000.f, sg = 1.f;
#pragma unroll 1
    for (int it = 0; it < NITER; ++it) {
        float inv = 1.0f / sg;
        float cur = 1.0f
            + ((e1 > 0.f) ? expf(-e1 * inv) : 1.0f)
            + ((e2 > 0.f) ? expf(-e2 * inv) : 1.0f)
            + ((e3 > 0.f) ? expf(-e3 * inv) : 1.0f)
            + ((e4 > 0.f) ? expf(-e4 * inv) : 1.0f);
        if (cur > 1.5f) m1 = sg; else m0 = sg;
        sg = 0.5f * (m0 + m1);
    }
    g_rhoz[r] = rho;
    g_sigz[r] = sg;
}

// ======================= K4: W1 / S + rowsum =======================
__global__ void k_w1s(float* __restrict__ W1a, float* __restrict__ S,
                      float* __restrict__ W1b) {
    int row  = blockIdx.x * 8 + (threadIdx.x >> 5);
    int lane = threadIdx.x & 31;
    float rho = g_rhoz[row];
    float invs = 1.0f / g_sigz[row];
    const float* dr = g_d + (size_t)row * KK;
    float w[32];
    float s = 0.f;
#pragma unroll
    for (int q = 0; q < 8; ++q) {
        float4 v = *(const float4*)&dr[q * 128 + lane * 4];
        float w0 = (v.x - rho > 0.f) ? expf(-(v.x - rho) * invs) : 1.0f;
        float w1 = (v.y - rho > 0.f) ? expf(-(v.y - rho) * invs) : 1.0f;
        float w2 = (v.z - rho > 0.f) ? expf(-(v.z - rho) * invs) : 1.0f;
        float w3 = (v.w - rho > 0.f) ? expf(-(v.w - rho) * invs) : 1.0f;
        w[q * 4 + 0] = w0; w[q * 4 + 1] = w1; w[q * 4 + 2] = w2; w[q * 4 + 3] = w3;
        s += (w0 + w1) + (w2 + w3);
    }
#pragma unroll
    for (int off = 16; off > 0; off >>= 1)
        s += __shfl_xor_sync(0xffffffffu, s, off);
    float rinv = 1.0f / s;
    size_t base = (size_t)row * KK;
#pragma unroll
    for (int q = 0; q < 8; ++q) {
        size_t o = base + q * 128 + lane * 4;
        float4 wv = make_float4(w[q * 4], w[q * 4 + 1], w[q * 4 + 2], w[q * 4 + 3]);
        float4 sv = make_float4(wv.x * rinv, wv.y * rinv, wv.z * rinv, wv.w * rinv);
        *(float4*)&W1a[o] = wv;
        *(float4*)&W1b[o] = wv;
        *(float4*)&S[o]   = sv;
    }
}

// ======================= K5: colsum(S) partials + merge =======================
__global__ void k_cspart(const float* __restrict__ S) {
    int col = blockIdx.x * 128 + threadIdx.x;
    const float* p = S + (size_t)blockIdx.y * (NN / 64) * KK + col;
    float acc = 0.f;
#pragma unroll 4
    for (int r = 0; r < NN / 64; ++r) acc += p[(size_t)r * KK];
    g_cspart[blockIdx.y * KK + col] = acc;
}

__global__ void k_csmerge() {
    int col = threadIdx.x;
    float acc = 0.f;
#pragma unroll
    for (int c = 0; c < 64; ++c) acc += g_cspart[c * KK + col];
    g_icolsum[col] = 1.0f / acc;
}

// ======================= K6: D =======================
__global__ void k_D(const float* __restrict__ S, float* __restrict__ D) {
    int row  = blockIdx.x * 8 + (threadIdx.x >> 5);
    int lane = threadIdx.x & 31;
    const float* sr = S + (size_t)row * KK;
    float t[32];
    float acc = 0.f;
#pragma unroll
    for (int q = 0; q < 8; ++q) {
        float4 v  = *(const float4*)&sr[q * 128 + lane * 4];
        float4 ic = *(const float4*)&g_icolsum[q * 128 + lane * 4];
        float t0 = v.x * v.x * ic.x;
        float t1 = v.y * v.y * ic.y;
        float t2 = v.z * v.z * ic.z;
        float t3 = v.w * v.w * ic.w;
        t[q * 4 + 0] = t0; t[q * 4 + 1] = t1; t[q * 4 + 2] = t2; t[q * 4 + 3] = t3;
        acc += (t0 + t1) + (t2 + t3);
    }
#pragma unroll
    for (int off = 16; off > 0; off >>= 1)
        acc += __shfl_xor_sync(0xffffffffu, acc, off);
    float rinv = 1.0f / acc;
    size_t base = (size_t)row * KK;
#pragma unroll
    for (int q = 0; q < 8; ++q) {
        size_t o = base + q * 128 + lane * 4;
        *(float4*)&D[o] = make_float4(t[q * 4] * rinv, t[q * 4 + 1] * rinv,
                                      t[q * 4 + 2] * rinv, t[q * 4 + 3] * rinv);
    }
}

// ======================= launch =======================
extern "C" void kernel_launch(void* const* d_in, const int* in_sizes, int n_in,
                              void* d_out, int out_size) {
    const float* Z  = (const float*)d_in[0];
    const float* MU = (const float*)d_in[1];
    float* out = (float*)d_out;
    float* W1a = out;
    float* S   = out + NKELT;
    float* W1b = out + 2 * NKELT;
    float* D   = out + 3 * NKELT;

    float *pa, *pb;
    cudaGetSymbolAddress((void**)&pa, g_a);
    cudaGetSymbolAddress((void**)&pb, g_b);

    k_stats<<<NN / 8, 256>>>(Z, pa,  2.0f * EPSF, 512.0f * EPSF * EPSF);
    k_stats<<<KK / 8, 256>>>(MU, pb, -2.0f * EPSF, 0.0f);
    k_gemm<<<dim3(KK / 128, NN / 128), 256>>>(Z, MU);
    k_rowtop5<<<NN / 8, 256>>>();
    k_solve<<<NN / 256, 256>>>();
    k_w1s<<<NN / 8, 256>>>(W1a, S, W1b);
    k_cspart<<<dim3(KK / 128, 64), 128>>>(S);
    k_csmerge<<<1, KK>>>();
    k_D<<<NN / 8, 256>>>(S, D);
}

// round 4
// speedup vs baseline: 2.2409x; 2.2409x over previous
#include <cuda_runtime.h>
#include <cuda_bf16.h>
#include <math.h>
#include <stdint.h>

#define NN    32768
#define KK    1024
#define DHH   512
#define KC3   1536        // 3*DHH split-K
#define EPSF  1e-5f
#define NITER 150
#define FBIG  3.402823466e38f
#define NKELT ((size_t)NN * KK)

// Unified GEMM launch config (both paths): tile 128(M) x 256(N), 256 threads
#define MT 128
#define NT 256
#define SMEM_TOT 102400

// tcgen05 path constants
#define TC_KCH   64
#define TC_NSTG  2
#define TC_NCH   (KC3 / TC_KCH)     // 24
#define TC_ASTG  (MT * 128)         // 16 KB
#define TC_BSTG  (NT * 128)         // 32 KB
#define TC_STGB  (TC_ASTG + TC_BSTG)

// mma.sync path constants
#define MM_KCH   32
#define MM_NCH   (KC3 / MM_KCH)     // 48
#define MM_ROWB  80                 // 64B data + 16B pad (bank shift 20 -> conflict-free)
#define MM_STAGE ((MT + NT) * MM_ROWB)

#if defined(__CUDA_ARCH_FEAT_SM103_ALL) || defined(__CUDA_ARCH_FEAT_SM100_ALL) || defined(__CUDA_ARCH_FEAT_SM101_ALL)
#define TC_OK 1
#else
#define TC_OK 0
#endif

// ---- static device scratch ----
__device__ __align__(16) float g_d[NN * KK];
__device__ __align__(16) __nv_bfloat16 g_zc[(size_t)NN * KC3];
__device__ __align__(16) __nv_bfloat16 g_mc[(size_t)KK * KC3];
__device__ float g_a[NN];
__device__ float g_b[KK];
__device__ float g_relz[NN * 5];
__device__ float g_rhoz[NN], g_sigz[NN];
__device__ float g_cspart[64 * KK];
__device__ float g_icolsum[KK];

// ---- helpers ----
__device__ __forceinline__ uint32_t s2u(const void* p) {
    uint32_t a;
    asm("{ .reg .u64 t; cvta.to.shared.u64 t, %1; cvt.u32.u64 %0, t; }"
        : "=r"(a) : "l"(p));
    return a;
}
__device__ __forceinline__ uint32_t swz(uint32_t o) { return o ^ ((o >> 3) & 0x70); }
__device__ __forceinline__ void cpa16(uint32_t dst, const void* src) {
    asm volatile("cp.async.cg.shared.global [%0], [%1], 16;" :: "r"(dst), "l"(src));
}

__device__ __forceinline__ void mma16816(float* c, const uint32_t* a, const uint32_t* b) {
    asm volatile("mma.sync.aligned.m16n8k16.row.col.f32.bf16.bf16.f32 "
        "{%0,%1,%2,%3}, {%4,%5,%6,%7}, {%8,%9}, {%0,%1,%2,%3};"
        : "+f"(c[0]), "+f"(c[1]), "+f"(c[2]), "+f"(c[3])
        : "r"(a[0]), "r"(a[1]), "r"(a[2]), "r"(a[3]), "r"(b[0]), "r"(b[1]));
}

#if TC_OK
__device__ __forceinline__ uint64_t mkdesc(uint32_t addr) {
    const uint64_t base = (uint64_t(2) << 61) | (uint64_t(1) << 46)
                        | (uint64_t(64) << 32) | (uint64_t(1) << 16);
    return base | ((uint64_t)(addr >> 4) & 0x3FFF);
}
__device__ __forceinline__ void mma_f16_ss(uint32_t d, uint64_t a, uint64_t b,
                                           uint32_t idesc, uint32_t en) {
    asm volatile(
        "{\n\t.reg .pred p;\n\tsetp.ne.u32 p, %4, 0;\n\t"
        "tcgen05.mma.cta_group::1.kind::f16 [%0], %1, %2, %3, {%5,%5,%5,%5}, p;\n\t}"
        :: "r"(d), "l"(a), "l"(b), "r"(idesc), "r"(en), "r"(0u) : "memory");
}
__device__ __forceinline__ void mbar_init(uint32_t m, uint32_t cnt) {
    asm volatile("mbarrier.init.shared.b64 [%0], %1;" :: "r"(m), "r"(cnt) : "memory");
}
__device__ __forceinline__ void mbar_wait(uint32_t m, uint32_t parity) {
    asm volatile(
        "{\n\t.reg .pred P1;\n\t"
        "WL_%=:\n\t"
        "mbarrier.try_wait.parity.acquire.cta.shared::cta.b64 P1, [%0], %1, 0x989680;\n\t"
        "@P1 bra.uni WD_%=;\n\t"
        "bra.uni WL_%=;\n\t"
        "WD_%=:\n\t}"
        :: "r"(m), "r"(parity) : "memory");
}
#endif

// ---- sorted smallest-5 insertion ----
#define INS5(v, a0, a1, a2, a3, a4) do {                          \
    float _v = (v);                                               \
    if (_v < a4) {                                                \
        a4 = _v;                                                  \
        if (a4 < a3) { float _t = a3; a3 = a4; a4 = _t; }         \
        if (a3 < a2) { float _t = a2; a2 = a3; a3 = _t; }         \
        if (a2 < a1) { float _t = a1; a1 = a2; a2 = _t; }         \
        if (a1 < a0) { float _t = a0; a0 = a1; a1 = _t; }         \
    }                                                             \
} while (0)

// ======================= K0: row stats =======================
__global__ void k_stats(const float* __restrict__ P, float* __restrict__ out,
                        float c2, float cadd) {
    int row  = blockIdx.x * 8 + (threadIdx.x >> 5);
    int lane = threadIdx.x & 31;
    const float* p = P + (size_t)row * DHH;
    float s = 0.f, ss = 0.f;
#pragma unroll
    for (int q = 0; q < 4; ++q) {
        float4 v = *(const float4*)&p[q * 128 + lane * 4];
        s  += (v.x + v.y) + (v.z + v.w);
        ss += v.x * v.x + v.y * v.y + v.z * v.z + v.w * v.w;
    }
#pragma unroll
    for (int off = 16; off > 0; off >>= 1) {
        s  += __shfl_xor_sync(0xffffffffu, s, off);
        ss += __shfl_xor_sync(0xffffffffu, ss, off);
    }
    if (lane == 0) out[row] = ss + c2 * s + cadd;
}

// ======================= K0b: fp32 -> bf16 hi/lo split-concat =======================
// lo_slot==1: [hi | lo | hi] (Z);  lo_slot==2: [hi | hi | lo] (MU)
__global__ void k_cvt(const float* __restrict__ X, __nv_bfloat16* __restrict__ C,
                      int lo_slot) {
    size_t idx = (size_t)blockIdx.x * 256 + threadIdx.x;
    size_t row = idx >> 7;
    int    c4  = ((int)idx & 127) << 2;
    float4 v = *(const float4*)&X[row * DHH + c4];
    float f[4] = {v.x, v.y, v.z, v.w};
    unsigned short hu[4], lu[4];
#pragma unroll
    for (int i = 0; i < 4; ++i) {
        __nv_bfloat16 h = __float2bfloat16(f[i]);
        __nv_bfloat16 l = __float2bfloat16(f[i] - __bfloat162float(h));
        hu[i] = __bfloat16_as_ushort(h);
        lu[i] = __bfloat16_as_ushort(l);
    }
    uint2 hv = make_uint2(((uint32_t)hu[1] << 16) | hu[0],
                          ((uint32_t)hu[3] << 16) | hu[2]);
    uint2 lv = make_uint2(((uint32_t)lu[1] << 16) | lu[0],
                          ((uint32_t)lu[3] << 16) | lu[2]);
    __nv_bfloat16* base = C + row * KC3 + c4;
    *(uint2*)(base)        = hv;
    *(uint2*)(base + 512)  = (lo_slot == 1) ? lv : hv;
    *(uint2*)(base + 1024) = (lo_slot == 1) ? hv : lv;
}

// ======================= K1: GEMM + distance (dual path) =======================
__global__ void __launch_bounds__(256, 1) k_gemm() {
    extern __shared__ char smem_raw[];
    const int tid = threadIdx.x;
    const int wid = tid >> 5, lid = tid & 31;
    const int j0 = blockIdx.x * NT;
    const int i0 = blockIdx.y * MT;

#if TC_OK
    // ---------------- tcgen05 path ----------------
    uint32_t sb0 = s2u(smem_raw);
    uint32_t sb  = (sb0 + 1023) & ~1023u;
    char* smA = smem_raw + (sb - sb0);

    if (wid == 0) {
        asm volatile("tcgen05.alloc.cta_group::1.sync.aligned.shared::cta.b32 [%0], %1;"
                     :: "r"(sb), "r"(256u) : "memory");
        asm volatile("tcgen05.relinquish_alloc_permit.cta_group::1.sync.aligned;");
    }
    if (tid == 0) {
        mbar_init(sb + 16, 1);
        mbar_init(sb + 24, 1);
    }
    __syncthreads();
    uint32_t tmem;
    asm volatile("ld.shared.b32 %0, [%1];" : "=r"(tmem) : "r"(sb));

    const __nv_bfloat16* Zrow = g_zc + (size_t)i0 * KC3;
    const __nv_bfloat16* Mrow = g_mc + (size_t)j0 * KC3;
    const uint32_t stg_base = sb + 1024;
    const uint32_t idesc = (1u << 4) | (1u << 7) | (1u << 10)
                         | ((128u / 8) << 17) | ((128u / 16) << 24);

    auto load_chunk = [&](int c) {
        uint32_t ab = stg_base + (uint32_t)(c & 1) * TC_STGB;
        uint32_t bb = ab + TC_ASTG;
#pragma unroll
        for (int it = 0; it < 4; ++it) {            // A: 1024 x 16B
            int idx = tid + it * 256;
            int row = idx >> 3, q = idx & 7;
            cpa16(ab + swz((uint32_t)row * 128 + q * 16),
                  Zrow + (size_t)row * KC3 + c * TC_KCH + q * 8);
        }
#pragma unroll
        for (int it = 0; it < 8; ++it) {            // B: 2048 x 16B
            int idx = tid + it * 256;
            int row = idx >> 3, q = idx & 7;
            cpa16(bb + swz((uint32_t)row * 128 + q * 16),
                  Mrow + (size_t)row * KC3 + c * TC_KCH + q * 8);
        }
    };

    load_chunk(0);
    asm volatile("cp.async.commit_group;" ::: "memory");
    load_chunk(1);
    asm volatile("cp.async.commit_group;" ::: "memory");

#pragma unroll 1
    for (int kt = 0; kt < TC_NCH; ++kt) {
        asm volatile("cp.async.wait_group 1;" ::: "memory");
        __syncthreads();
        if (tid == 0) {
            asm volatile("fence.proxy.async.shared::cta;" ::: "memory");
            uint32_t ab = stg_base + (uint32_t)(kt & 1) * TC_STGB;
            uint64_t ad = mkdesc(ab);
            uint64_t bd = mkdesc(ab + TC_ASTG);
#pragma unroll
            for (int k = 0; k < 4; ++k) {
                uint32_t en = (kt | k) ? 1u : 0u;
                mma_f16_ss(tmem,       ad + 2 * k, bd + 2 * k,        idesc, en);
                mma_f16_ss(tmem + 128, ad + 2 * k, bd + 1024 + 2 * k, idesc, en);
            }
            asm volatile(
                "tcgen05.commit.cta_group::1.mbarrier::arrive::one.shared::cluster.b64 [%0];"
                :: "r"(sb + 16 + 8 * (kt & 1)) : "memory");
        }
        if (kt + 2 < TC_NCH) {
            mbar_wait(sb + 16 + 8 * (kt & 1), (kt >> 1) & 1);
            load_chunk(kt + 2);
        }
        asm volatile("cp.async.commit_group;" ::: "memory");
    }

    mbar_wait(sb + 16 + 8 * 1, 1);   // chunk 23: mbar1, 12th arrive -> phase 11 -> parity 1
    asm volatile("tcgen05.fence::after_thread_sync;" ::: "memory");

    if (wid < 4) {
        float* eb = (float*)(smA + 1024) + wid * (32 * 33);
        float a_l = g_a[i0 + wid * 32 + lid];
#pragma unroll 1
        for (int cb = 0; cb < 8; ++cb) {
            uint32_t r[32];
            asm volatile(
                "tcgen05.ld.sync.aligned.32x32b.x32.b32 "
                "{%0, %1, %2, %3, %4, %5, %6, %7, "
                " %8, %9, %10, %11, %12, %13, %14, %15, "
                " %16, %17, %18, %19, %20, %21, %22, %23, "
                " %24, %25, %26, %27, %28, %29, %30, %31}, [%32];"
                : "=r"(r[0]), "=r"(r[1]), "=r"(r[2]), "=r"(r[3]),
                  "=r"(r[4]), "=r"(r[5]), "=r"(r[6]), "=r"(r[7]),
                  "=r"(r[8]), "=r"(r[9]), "=r"(r[10]), "=r"(r[11]),
                  "=r"(r[12]), "=r"(r[13]), "=r"(r[14]), "=r"(r[15]),
                  "=r"(r[16]), "=r"(r[17]), "=r"(r[18]), "=r"(r[19]),
                  "=r"(r[20]), "=r"(r[21]), "=r"(r[22]), "=r"(r[23]),
                  "=r"(r[24]), "=r"(r[25]), "=r"(r[26]), "=r"(r[27]),
                  "=r"(r[28]), "=r"(r[29]), "=r"(r[30]), "=r"(r[31])
                : "r"(tmem + cb * 32));
            asm volatile("tcgen05.wait::ld.sync.aligned;" ::: "memory");
            float bj = g_b[j0 + cb * 32 + lid];
#pragma unroll
            for (int c = 0; c < 32; ++c) eb[lid * 33 + c] = __uint_as_float(r[c]);
            __syncwarp();
#pragma unroll
            for (int rr = 0; rr < 32; ++rr) {
                float p = eb[rr * 33 + lid];
                float a = __shfl_sync(0xffffffffu, a_l, rr);
                float d2 = fmaf(-2.0f, p, a + bj);
                g_d[(size_t)(i0 + wid * 32 + rr) * KK + j0 + cb * 32 + lid] =
                    sqrtf(fmaxf(d2, 0.0f));
            }
            __syncwarp();
        }
    }

    __syncthreads();
    if (tid == 0) {
        asm volatile("mbarrier.inval.shared.b64 [%0];" :: "r"(sb + 16) : "memory");
        asm volatile("mbarrier.inval.shared.b64 [%0];" :: "r"(sb + 24) : "memory");
    }
    __syncthreads();
    if (wid == 0)
        asm volatile("tcgen05.dealloc.cta_group::1.sync.aligned.b32 %0, %1;"
                     :: "r"(tmem), "r"(256u));

#else
    // ---------------- mma.sync fallback path ----------------
    const int g = lid >> 2, t = lid & 3;
    const int wm = wid >> 2, wn = wid & 3;      // warp tile 64(M) x 64(N)
    char* sm = smem_raw;
    uint32_t smu = s2u(sm);

    auto load_chunk = [&](int c) {
        uint32_t st = smu + (uint32_t)(c % 3) * MM_STAGE;
#pragma unroll
        for (int it = 0; it < 6; ++it) {            // 1536 x 16B per stage
            int idx = tid + it * 256;
            int row = idx >> 2, q = idx & 3;
            const __nv_bfloat16* src = (row < MT)
                ? g_zc + (size_t)(i0 + row) * KC3 + c * MM_KCH + q * 8
                : g_mc + (size_t)(j0 + row - MT) * KC3 + c * MM_KCH + q * 8;
            cpa16(st + (uint32_t)row * MM_ROWB + q * 16, src);
        }
    };

    float cacc[4][8][4];
#pragma unroll
    for (int mi = 0; mi < 4; ++mi)
#pragma unroll
        for (int ni = 0; ni < 8; ++ni)
#pragma unroll
            for (int q = 0; q < 4; ++q) cacc[mi][ni][q] = 0.f;

    load_chunk(0); asm volatile("cp.async.commit_group;" ::: "memory");
    load_chunk(1); asm volatile("cp.async.commit_group;" ::: "memory");
    load_chunk(2); asm volatile("cp.async.commit_group;" ::: "memory");

#pragma unroll 1
    for (int kt = 0; kt < MM_NCH; ++kt) {
        asm volatile("cp.async.wait_group 2;" ::: "memory");
        __syncthreads();
        const char* st = sm + (kt % 3) * MM_STAGE;
        const char* Ab = st + (wm * 64 + g) * MM_ROWB + t * 4;
        const char* Bb = st + MT * MM_ROWB + (wn * 64 + g) * MM_ROWB + t * 4;
#pragma unroll
        for (int ks = 0; ks < 2; ++ks) {
            uint32_t a[4][4], b[8][2];
#pragma unroll
            for (int mi = 0; mi < 4; ++mi) {
                const char* p = Ab + mi * 16 * MM_ROWB + ks * 32;
                a[mi][0] = *(const uint32_t*)(p);
                a[mi][1] = *(const uint32_t*)(p + 8 * MM_ROWB);
                a[mi][2] = *(const uint32_t*)(p + 16);
                a[mi][3] = *(const uint32_t*)(p + 8 * MM_ROWB + 16);
            }
#pragma unroll
            for (int ni = 0; ni < 8; ++ni) {
                const char* p = Bb + ni * 8 * MM_ROWB + ks * 32;
                b[ni][0] = *(const uint32_t*)(p);
                b[ni][1] = *(const uint32_t*)(p + 16);
            }
#pragma unroll
            for (int mi = 0; mi < 4; ++mi)
#pragma unroll
                for (int ni = 0; ni < 8; ++ni)
                    mma16816(cacc[mi][ni], a[mi], b[ni]);
        }
        __syncthreads();
        if (kt + 3 < MM_NCH) load_chunk(kt + 3);
        asm volatile("cp.async.commit_group;" ::: "memory");
    }

    // distance epilogue
#pragma unroll
    for (int mi = 0; mi < 4; ++mi) {
        int r0 = i0 + wm * 64 + mi * 16 + g;
        float a0 = g_a[r0], a1 = g_a[r0 + 8];
#pragma unroll
        for (int ni = 0; ni < 8; ++ni) {
            int cn = j0 + wn * 64 + ni * 8 + t * 2;
            float2 bb = *(const float2*)&g_b[cn];
            float2 o0, o1;
            o0.x = sqrtf(fmaxf(fmaf(-2.f, cacc[mi][ni][0], a0 + bb.x), 0.f));
            o0.y = sqrtf(fmaxf(fmaf(-2.f, cacc[mi][ni][1], a0 + bb.y), 0.f));
            o1.x = sqrtf(fmaxf(fmaf(-2.f, cacc[mi][ni][2], a1 + bb.x), 0.f));
            o1.y = sqrtf(fmaxf(fmaf(-2.f, cacc[mi][ni][3], a1 + bb.y), 0.f));
            *(float2*)&g_d[(size_t)r0 * KK + cn]       = o0;
            *(float2*)&g_d[(size_t)(r0 + 8) * KK + cn] = o1;
        }
    }
#endif
}

// ======================= K2: row top-5 =======================
__global__ void k_rowtop5() {
    int row  = blockIdx.x * 8 + (threadIdx.x >> 5);
    int lane = threadIdx.x & 31;
    const float* dr = g_d + (size_t)row * KK;
    float t0 = FBIG, t1 = FBIG, t2 = FBIG, t3 = FBIG, t4 = FBIG;
#pragma unroll 1
    for (int q = 0; q < 8; ++q) {
        float4 v = *(const float4*)&dr[q * 128 + lane * 4];
        float m = fminf(fminf(v.x, v.y), fminf(v.z, v.w));
        if (m < t4) {
            INS5(v.x, t0, t1, t2, t3, t4);
            INS5(v.y, t0, t1, t2, t3, t4);
            INS5(v.z, t0, t1, t2, t3, t4);
            INS5(v.w, t0, t1, t2, t3, t4);
        }
    }
#pragma unroll
    for (int off = 16; off > 0; off >>= 1) {
        float s0 = __shfl_xor_sync(0xffffffffu, t0, off);
        float s1 = __shfl_xor_sync(0xffffffffu, t1, off);
        float s2 = __shfl_xor_sync(0xffffffffu, t2, off);
        float s3 = __shfl_xor_sync(0xffffffffu, t3, off);
        float s4 = __shfl_xor_sync(0xffffffffu, t4, off);
        if (s0 < t4) {
            INS5(s0, t0, t1, t2, t3, t4);
            INS5(s1, t0, t1, t2, t3, t4);
            INS5(s2, t0, t1, t2, t3, t4);
            INS5(s3, t0, t1, t2, t3, t4);
            INS5(s4, t0, t1, t2, t3, t4);
        }
    }
    if (lane == 0) {
        float* o = g_relz + (size_t)row * 5;
        o[0] = t0; o[1] = t1; o[2] = t2; o[3] = t3; o[4] = t4;
    }
}

// ======================= K3: sigma bisection =======================
__global__ void k_solve() {
    int r = blockIdx.x * 256 + threadIdx.x;
    const float* rl = g_relz + (size_t)r * 5;
    float rho = rl[0];
    float e1 = rl[1] - rho, e2 = rl[2] - rho, e3 = rl[3] - rho, e4 = rl[4] - rho;
    float m0 = 0.f, m1 = 10000.f, sg = 1.f;
#pragma unroll 1
    for (int it = 0; it < NITER; ++it) {
        float inv = 1.0f / sg;
        float cur = 1.0f
            + ((e1 > 0.f) ? expf(-e1 * inv) : 1.0f)
            + ((e2 > 0.f) ? expf(-e2 * inv) : 1.0f)
            + ((e3 > 0.f) ? expf(-e3 * inv) : 1.0f)
            + ((e4 > 0.f) ? expf(-e4 * inv) : 1.0f);
        if (cur > 1.5f) m1 = sg; else m0 = sg;
        sg = 0.5f * (m0 + m1);
    }
    g_rhoz[r] = rho;
    g_sigz[r] = sg;
}

// ======================= K4: W1 / S + rowsum =======================
__global__ void k_w1s(float* __restrict__ W1a, float* __restrict__ S,
                      float* __restrict__ W1b) {
    int row  = blockIdx.x * 8 + (threadIdx.x >> 5);
    int lane = threadIdx.x & 31;
    float rho = g_rhoz[row];
    float invs = 1.0f / g_sigz[row];
    const float* dr = g_d + (size_t)row * KK;
    float w[32];
    float s = 0.f;
#pragma unroll
    for (int q = 0; q < 8; ++q) {
        float4 v = *(const float4*)&dr[q * 128 + lane * 4];
        float w0 = (v.x - rho > 0.f) ? expf(-(v.x - rho) * invs) : 1.0f;
        float w1 = (v.y - rho > 0.f) ? expf(-(v.y - rho) * invs) : 1.0f;
        float w2 = (v.z - rho > 0.f) ? expf(-(v.z - rho) * invs) : 1.0f;
        float w3 = (v.w - rho > 0.f) ? expf(-(v.w - rho) * invs) : 1.0f;
        w[q * 4 + 0] = w0; w[q * 4 + 1] = w1; w[q * 4 + 2] = w2; w[q * 4 + 3] = w3;
        s += (w0 + w1) + (w2 + w3);
    }
#pragma unroll
    for (int off = 16; off > 0; off >>= 1)
        s += __shfl_xor_sync(0xffffffffu, s, off);
    float rinv = 1.0f / s;
    size_t base = (size_t)row * KK;
#pragma unroll
    for (int q = 0; q < 8; ++q) {
        size_t o = base + q * 128 + lane * 4;
        float4 wv = make_float4(w[q * 4], w[q * 4 + 1], w[q * 4 + 2], w[q * 4 + 3]);
        float4 sv = make_float4(wv.x * rinv, wv.y * rinv, wv.z * rinv, wv.w * rinv);
        *(float4*)&W1a[o] = wv;
        *(float4*)&W1b[o] = wv;
        *(float4*)&S[o]   = sv;
    }
}

// ======================= K5: colsum(S) =======================
__global__ void k_cspart(const float* __restrict__ S) {
    int col = blockIdx.x * 128 + threadIdx.x;
    const float* p = S + (size_t)blockIdx.y * (NN / 64) * KK + col;
    float acc = 0.f;
#pragma unroll 4
    for (int r = 0; r < NN / 64; ++r) acc += p[(size_t)r * KK];
    g_cspart[blockIdx.y * KK + col] = acc;
}

__global__ void k_csmerge() {
    int col = threadIdx.x;
    float acc = 0.f;
#pragma unroll
    for (int c = 0; c < 64; ++c) acc += g_cspart[c * KK + col];
    g_icolsum[col] = 1.0f / acc;
}

// ======================= K6: D =======================
__global__ void k_D(const float* __restrict__ S, float* __restrict__ D) {
    int row  = blockIdx.x * 8 + (threadIdx.x >> 5);
    int lane = threadIdx.x & 31;
    const float* sr = S + (size_t)row * KK;
    float t[32];
    float acc = 0.f;
#pragma unroll
    for (int q = 0; q < 8; ++q) {
        float4 v  = *(const float4*)&sr[q * 128 + lane * 4];
        float4 ic = *(const float4*)&g_icolsum[q * 128 + lane * 4];
        float t0 = v.x * v.x * ic.x;
        float t1 = v.y * v.y * ic.y;
        float t2 = v.z * v.z * ic.z;
        float t3 = v.w * v.w * ic.w;
        t[q * 4 + 0] = t0; t[q * 4 + 1] = t1; t[q * 4 + 2] = t2; t[q * 4 + 3] = t3;
        acc += (t0 + t1) + (t2 + t3);
    }
#pragma unroll
    for (int off = 16; off > 0; off >>= 1)
        acc += __shfl_xor_sync(0xffffffffu, acc, off);
    float rinv = 1.0f / acc;
    size_t base = (size_t)row * KK;
#pragma unroll
    for (int q = 0; q < 8; ++q) {
        size_t o = base + q * 128 + lane * 4;
        *(float4*)&D[o] = make_float4(t[q * 4] * rinv, t[q * 4 + 1] * rinv,
                                      t[q * 4 + 2] * rinv, t[q * 4 + 3] * rinv);
    }
}

// ======================= launch =======================
extern "C" void kernel_launch(void* const* d_in, const int* in_sizes, int n_in,
                              void* d_out, int out_size) {
    const float* Z  = (const float*)d_in[0];
    const float* MU = (const float*)d_in[1];
    float* out = (float*)d_out;
    float* W1a = out;
    float* S   = out + NKELT;
    float* W1b = out + 2 * NKELT;
    float* D   = out + 3 * NKELT;

    float *pa, *pb;
    __nv_bfloat16 *pzc, *pmc;
    cudaGetSymbolAddress((void**)&pa, g_a);
    cudaGetSymbolAddress((void**)&pb, g_b);
    cudaGetSymbolAddress((void**)&pzc, g_zc);
    cudaGetSymbolAddress((void**)&pmc, g_mc);

    cudaFuncSetAttribute(k_gemm, cudaFuncAttributeMaxDynamicSharedMemorySize,
                         SMEM_TOT);

    k_stats<<<NN / 8, 256>>>(Z, pa,  2.0f * EPSF, 512.0f * EPSF * EPSF);
    k_stats<<<KK / 8, 256>>>(MU, pb, -2.0f * EPSF, 0.0f);
    k_cvt<<<(NN * 128) / 256, 256>>>(Z, pzc, 1);
    k_cvt<<<(KK * 128) / 256, 256>>>(MU, pmc, 2);
    k_gemm<<<dim3(KK / NT, NN / MT), 256, SMEM_TOT>>>();
    k_rowtop5<<<NN / 8, 256>>>();
    k_solve<<<NN / 256, 256>>>();
    k_w1s<<<NN / 8, 256>>>(W1a, S, W1b);
    k_cspart<<<dim3(KK / 128, 64), 128>>>(S);
    k_csmerge<<<1, KK>>>();
    k_D<<<NN / 8, 256>>>(S, D);
}